// round 15
// baseline (speedup 1.0000x reference)
#include <cuda_runtime.h>

#define NROWS 128
#define LEN   2048
#define NK    6
#define NT    256                 // 8 warps per block
#define NWARP 8
#define NB    512                 // 4096 warp-tasks = 128 rows x 32 segments
#define NTASK 4096
#define PITCH 217                 // SLOT(192)=216 -> 217 float4 per warp slice
#define FIXSCALE 1099511627776.0f // 2^40
#define CNT_ONE  (1ull << 54)
#define SUM_MASK (CNT_ONE - 1ull)

// bits [54..63]: completed-block count; bits [0..53]: fixed-point (2^-40) loss sum.
__device__ unsigned long long g_accum = 0ull;

// pad one float4 per 8 entries to keep LDS/STS.128 near the 4-phase minimum.
#define SLOT(i) ((i) + ((i) >> 3))

__device__ __forceinline__ float4 f4add(float4 a, float4 b) {
    return make_float4(a.x + b.x, a.y + b.y, a.z + b.z, a.w + b.w);
}

__global__ void __launch_bounds__(NT, 4) entropy_fused(
    const float* __restrict__ in, const float* __restrict__ tg, float* __restrict__ out)
{
    __shared__ float4 Psh[NWARP * PITCH];   // per-warp private prefix slices
    __shared__ float  redk[NWARP];

    const int tid  = threadIdx.x;
    const int lane = tid & 31, w = tid >> 5;
    const int task = (blockIdx.x << 3) + w;        // 0..4095
    const int row  = task >> 5;
    const int S    = (task & 31) << 6;             // warp's first window-start

    // ---- load 6 consecutive elements per lane (3 float2 per tensor), guarded ----
    const float* xi = in + (size_t)row * LEN;
    const float* xt = tg + (size_t)row * LEN;
    const int e = S + 6 * lane;                    // max 1984+186 = 2170
    float2 A0 = make_float2(0.f,0.f), A1 = A0, A2 = A0, B0 = A0, B1 = A0, B2 = A0;
    if (e < LEN)     { A0 = *(const float2*)(xi + e);     B0 = *(const float2*)(xt + e); }
    if (e + 2 < LEN) { A1 = *(const float2*)(xi + e + 2); B1 = *(const float2*)(xt + e + 2); }
    if (e + 4 < LEN) { A2 = *(const float2*)(xi + e + 4); B2 = *(const float2*)(xt + e + 4); }
    const float ax[6] = {A0.x,A0.y,A1.x,A1.y,A2.x,A2.y};
    const float bx[6] = {B0.x,B0.y,B1.x,B1.y,B2.x,B2.y};

    // ---- register-local inclusive prefix of (e^a, a e^a, e^b, b e^b) ----
    float4 v[6];
    {
        float4 run = make_float4(0.f,0.f,0.f,0.f);
        #pragma unroll
        for (int j = 0; j < 6; j++) {
            float ea = __expf(ax[j]);
            float eb = __expf(bx[j]);
            run.x += ea;  run.y += ax[j] * ea;
            run.z += eb;  run.w += bx[j] * eb;
            v[j] = run;
        }
    }

    // ---- warp-only scan of per-lane totals (no block barrier in main path) ----
    float4 t = v[5];
    #pragma unroll
    for (int off = 1; off < 32; off <<= 1) {
        float4 n;
        n.x = __shfl_up_sync(0xffffffffu, t.x, off);
        n.y = __shfl_up_sync(0xffffffffu, t.y, off);
        n.z = __shfl_up_sync(0xffffffffu, t.z, off);
        n.w = __shfl_up_sync(0xffffffffu, t.w, off);
        if (lane >= off) t = f4add(t, n);
    }
    const float4 ex = make_float4(t.x - v[5].x, t.y - v[5].y,
                                  t.z - v[5].z, t.w - v[5].w);

    // ---- write local prefix (entries 1..192) into this warp's smem slice ----
    float4* Pw = Psh + w * PITCH;
    #pragma unroll
    for (int j = 0; j < 6; j++) {
        int idx = 6 * lane + j + 1;
        Pw[SLOT(idx)] = f4add(v[j], ex);
    }
    if (lane == 0) Pw[0] = make_float4(0.f,0.f,0.f,0.f);
    __syncwarp();

    // ---- windows: starts S+lane, S+lane+32, all 6 k ----
    // lo[j] = P[lane + 32 j], j = 0..5. For k in {32,64,128} the hi operand of
    // window start sl = lane+32j is exactly lo[j + k/32] -> register, no LDS.
    // Only k in {4,8,16} read hi from smem.
    // ent1 - ent2 = (S1*Z2 - S2*Z1)*r - log(Z1^2 * r), r = 1/(Z1*Z2)
    float4 lo[6];
    #pragma unroll
    for (int j = 0; j < 6; j++) lo[j] = Pw[SLOT(lane + 32 * j)];

    float acc = 0.0f;
    #pragma unroll
    for (int kk = 0; kk < NK; kk++) {
        const int   k  = 4 << kk;
        const int   nW = LEN - k + 1;
        const float wk = 1.0f / (128.0f * (float)nW);
        float acck = 0.0f;
        #pragma unroll
        for (int j = 0; j < 2; j++) {
            const int sl = lane + 32 * j;
            if (S + sl < nW) {
                float4 hi = (k >= 32) ? lo[j + (k >> 5)] : Pw[SLOT(sl + k)];
                float z1 = hi.x - lo[j].x, f1 = hi.y - lo[j].y;
                float z2 = hi.z - lo[j].z, f2 = hi.w - lo[j].w;
                float r = __fdividef(1.0f, z1 * z2);
                float d = fmaf(f1 * z2 - f2 * z1, r, -__logf(z1 * z1 * r));
                acck += fabsf(d);
            }
        }
        acc = fmaf(acck, wk, acc);
    }

    // ---- warp reduce, then 8-warp block reduce ----
    #pragma unroll
    for (int off = 16; off; off >>= 1) acc += __shfl_down_sync(0xffffffffu, acc, off);
    if (lane == 0) redk[w] = acc;
    __syncthreads();
    if (tid == 0) {
        float s = 0.0f;
        #pragma unroll
        for (int i = 0; i < NWARP; i++) s += redk[i];
        // single fixed-point atomic: order-invariant integer sum -> deterministic
        unsigned long long add = CNT_ONE + (unsigned long long)__float2ll_rn(s * FIXSCALE);
        unsigned long long old = atomicAdd(&g_accum, add);
        if ((old >> 54) == NB - 1) {                 // final arrival
            unsigned long long tot = (old + add) & SUM_MASK;
            out[0] = (float)((double)tot * (1.0 / 1099511627776.0));
            g_accum = 0ull;                          // reset for next graph replay
        }
    }
}

extern "C" void kernel_launch(void* const* d_in, const int* in_sizes, int n_in,
                              void* d_out, int out_size) {
    const float* in = (const float*)d_in[0];
    const float* tg = (const float*)d_in[1];
    entropy_fused<<<NB, NT>>>(in, tg, (float*)d_out);
}

// round 16
// speedup vs baseline: 1.0220x; 1.0220x over previous
#include <cuda_runtime.h>

#define NROWS 128
#define LEN   2048
#define NK    6
#define NT    128                 // 4 warps per block
#define NB    512                 // 2048 warp-tasks = 128 rows x 16 segments
#define PITCH 289                 // SLOT(256)=288 -> 289 float4 per warp slice
#define FIXSCALE 1099511627776.0f // 2^40
#define CNT_ONE  (1ull << 54)
#define SUM_MASK (CNT_ONE - 1ull)

// bits [54..63]: completed-block count; bits [0..53]: fixed-point (2^-40) loss sum.
__device__ unsigned long long g_accum = 0ull;

// pad one float4 per 8 entries: scan stores and window reads stay near the
// 4-phase LDS.128/STS.128 minimum.
#define SLOT(i) ((i) + ((i) >> 3))

__device__ __forceinline__ float4 f4add(float4 a, float4 b) {
    return make_float4(a.x + b.x, a.y + b.y, a.z + b.z, a.w + b.w);
}

__global__ void __launch_bounds__(NT, 4) entropy_fused(
    const float* __restrict__ in, const float* __restrict__ tg, float* __restrict__ out)
{
    __shared__ float4 Psh[4 * PITCH];   // per-warp private prefix slices
    __shared__ float  redk[4];

    const int tid  = threadIdx.x;
    const int lane = tid & 31, w = tid >> 5;
    const int row  = blockIdx.x >> 2;
    const int S    = ((blockIdx.x & 3) << 9) + (w << 7);   // warp's first window-start

    // ---- load 8 consecutive elements per lane, UNGUARDED via clamp ----
    // Prefix entries past the row end are garbage-but-harmless: they come after
    // all valid entries, and every window touching them fails the S+sl<nW guard.
    const float* xi = in + (size_t)row * LEN;
    const float* xt = tg + (size_t)row * LEN;
    int e = S + 8 * lane;
    e = (e > LEN - 8) ? (LEN - 8) : e;           // clamp instead of predicate
    const float4 A0 = *(const float4*)(xi + e);
    const float4 A1 = *(const float4*)(xi + e + 4);
    const float4 B0 = *(const float4*)(xt + e);
    const float4 B1 = *(const float4*)(xt + e + 4);
    const float ax[8] = {A0.x,A0.y,A0.z,A0.w,A1.x,A1.y,A1.z,A1.w};
    const float bx[8] = {B0.x,B0.y,B0.z,B0.w,B1.x,B1.y,B1.z,B1.w};

    // ---- register-local inclusive prefix of (e^a, a e^a, e^b, b e^b) ----
    float4 v[8];
    {
        float4 run = make_float4(0.f,0.f,0.f,0.f);
        #pragma unroll
        for (int j = 0; j < 8; j++) {
            float ea = __expf(ax[j]);
            float eb = __expf(bx[j]);
            run.x += ea;  run.y += ax[j] * ea;
            run.z += eb;  run.w += bx[j] * eb;
            v[j] = run;
        }
    }

    // ---- warp-only scan of per-lane totals (no block barrier in main path) ----
    float4 t = v[7];
    #pragma unroll
    for (int off = 1; off < 32; off <<= 1) {
        float4 n;
        n.x = __shfl_up_sync(0xffffffffu, t.x, off);
        n.y = __shfl_up_sync(0xffffffffu, t.y, off);
        n.z = __shfl_up_sync(0xffffffffu, t.z, off);
        n.w = __shfl_up_sync(0xffffffffu, t.w, off);
        if (lane >= off) t = f4add(t, n);
    }
    const float4 ex = make_float4(t.x - v[7].x, t.y - v[7].y,
                                  t.z - v[7].z, t.w - v[7].w);

    // ---- write local prefix (entries 1..256) into this warp's smem slice ----
    float4* Pw = Psh + w * PITCH;
    #pragma unroll
    for (int j = 0; j < 8; j++) {
        int idx = 8 * lane + j + 1;
        Pw[SLOT(idx)] = f4add(v[j], ex);
    }
    if (lane == 0) Pw[0] = make_float4(0.f,0.f,0.f,0.f);
    __syncwarp();

    // ---- windows ----
    // lo[j] = P[lane + 32 j], j = 0..7. For k in {32,64,128} the hi operand of
    // window start sl = lane+32j is exactly lo[j + k/32] -> register, no LDS.
    // Only k in {4,8,16} read hi from smem.
    // ent1 - ent2 = (S1*Z2 - S2*Z1)*r - log(Z1^2 * r), r = 1/(Z1*Z2)
    float4 lo[8];
    #pragma unroll
    for (int j = 0; j < 8; j++) lo[j] = Pw[SLOT(lane + 32 * j)];

    float acc = 0.0f;
    #pragma unroll
    for (int kk = 0; kk < NK; kk++) {
        const int   k  = 4 << kk;
        const int   nW = LEN - k + 1;
        const float wk = 1.0f / (128.0f * (float)nW);
        float acck = 0.0f;
        #pragma unroll
        for (int j = 0; j < 4; j++) {
            const int sl = lane + 32 * j;
            if (S + sl < nW) {
                float4 hi = (k >= 32) ? lo[j + (k >> 5)] : Pw[SLOT(sl + k)];
                float z1 = hi.x - lo[j].x, f1 = hi.y - lo[j].y;
                float z2 = hi.z - lo[j].z, f2 = hi.w - lo[j].w;
                float r = __fdividef(1.0f, z1 * z2);
                float d = fmaf(f1 * z2 - f2 * z1, r, -__logf(z1 * z1 * r));
                acck += fabsf(d);
            }
        }
        acc = fmaf(acck, wk, acc);
    }

    // ---- warp reduce, then tiny 4-warp block reduce ----
    #pragma unroll
    for (int off = 16; off; off >>= 1) acc += __shfl_down_sync(0xffffffffu, acc, off);
    if (lane == 0) redk[w] = acc;
    __syncthreads();
    if (tid == 0) {
        float s = redk[0] + redk[1] + redk[2] + redk[3];
        // single fixed-point atomic: order-invariant integer sum -> deterministic
        unsigned long long add = CNT_ONE + (unsigned long long)__float2ll_rn(s * FIXSCALE);
        unsigned long long old = atomicAdd(&g_accum, add);
        if ((old >> 54) == NB - 1) {                 // final arrival
            unsigned long long tot = (old + add) & SUM_MASK;
            out[0] = (float)((double)tot * (1.0 / 1099511627776.0));
            g_accum = 0ull;                          // reset for next graph replay
        }
    }
}

extern "C" void kernel_launch(void* const* d_in, const int* in_sizes, int n_in,
                              void* d_out, int out_size) {
    const float* in = (const float*)d_in[0];
    const float* tg = (const float*)d_in[1];
    entropy_fused<<<NB, NT>>>(in, tg, (float*)d_out);
}